// round 3
// baseline (speedup 1.0000x reference)
#include <cuda_runtime.h>

#define NTOK 32768
#define DD   256
#define VV   100000
#define NN2  1000
#define NN3  100

// ------------------------- device scratch -------------------------
__device__ float g_Wihf[1024*256], g_Whhf[1024*256], g_Wihb[1024*256], g_Whhb[1024*256];
__device__ float g_bf[1024], g_bb[1024];
__device__ float g_sum2[NN2*256], g_cnt2[NN2], g_sum3[NN3*256], g_cnt3[NN3];
__device__ float g_l2cat[1001*256], g_l3cat[101*256], g_rootcat[2*256];
__device__ float g_P2f[1001*1024], g_P3f[101*1024], g_Prf[2*1024];
__device__ float g_P2b[1001*1024], g_P3b[101*1024], g_Prb[2*1024];
__device__ float g_h1[2*256], g_c1[2*256], g_h2[101*256], g_c2[101*256];
__device__ float g_h3[1001*256], g_c3[1001*256], g_HPb[1001*1024];
__device__ int   g_i01[101], g_i3[1001];
__device__ float g_X0[NTOK*256];
__device__ int   g_sidx[NTOK], g_iF3[NTOK], g_iFr[NTOK];
__device__ float g_Ha[NTOK*256], g_Ca[NTOK*256], g_Hc[NTOK*256], g_Cc[NTOK*256];

// ------------------------- helpers -------------------------
__device__ __forceinline__ float tf32r(float x){
    unsigned u; asm("cvt.rna.tf32.f32 %0, %1;" : "=r"(u) : "f"(x));
    return __uint_as_float(u);
}
__device__ __forceinline__ float sigf(float x){ return 1.f/(1.f+__expf(-x)); }
__device__ __forceinline__ float tanhfast(float x){
    float y; asm("tanh.approx.f32 %0, %1;" : "=f"(y) : "f"(x)); return y;
}
__device__ __forceinline__ void mma8(float* d, const unsigned* a, const unsigned* b){
    asm volatile("mma.sync.aligned.m16n8k8.row.col.f32.tf32.tf32.f32 "
        "{%0,%1,%2,%3},{%4,%5,%6,%7},{%8,%9},{%0,%1,%2,%3};"
        : "+f"(d[0]), "+f"(d[1]), "+f"(d[2]), "+f"(d[3])
        : "r"(a[0]), "r"(a[1]), "r"(a[2]), "r"(a[3]), "r"(b[0]), "r"(b[1]));
}

// ------------------------- small kernels -------------------------
__global__ void k_zero(){
    int i = blockIdx.x*256 + threadIdx.x;
    if (i < NN2*256) g_sum2[i] = 0.f;
    if (i < NN2)     g_cnt2[i] = 0.f;
    if (i < NN3*256) g_sum3[i] = 0.f;
    if (i < NN3)     g_cnt3[i] = 0.f;
}

// permute weights to gate-interleaved order: out col p=4u+g <- orig row g*256+u
__global__ void k_prep(const float* wih, const float* whh, const float* bih, const float* bhh,
                       float* wihP, float* whhP, float* bP){
    int i = blockIdx.x*256 + threadIdx.x;       // over 1024*256
    int p = i >> 8, k = i & 255;
    int u = p >> 2, g = p & 3;
    int src = g*256 + u;
    wihP[i] = wih[src*256 + k];
    whhP[i] = whh[src*256 + k];
    if (k == 0) bP[p] = bih[src] + bhh[src];
}

__global__ void k_seg2(const float* embed, const int* l2){
    int leaf = blockIdx.x;                       // 0..V-1
    if (leaf == 0) return;                       // leaves start at 1
    int d = threadIdx.x;
    int j = l2[leaf];
    atomicAdd(&g_sum2[j*256 + d], embed[(size_t)leaf*256 + d]);
    if (d == 0) atomicAdd(&g_cnt2[j], 1.f);
}

__global__ void k_lvl2(const int* l3){
    int j = blockIdx.x, d = threadIdx.x;         // 1001 blocks
    if (j == 1000){ g_l2cat[j*256 + d] = 0.f; return; }
    float c = fmaxf(g_cnt2[j], 1.f);
    float v = g_sum2[j*256 + d] / c;
    g_l2cat[j*256 + d] = v;
    int k = l3[j];
    atomicAdd(&g_sum3[k*256 + d], v);
    if (d == 0) atomicAdd(&g_cnt3[k], 1.f);
}

__global__ void k_lvl3(){
    int k = blockIdx.x, d = threadIdx.x;         // 101 blocks
    if (k == 100){ g_l3cat[k*256 + d] = 0.f; return; }
    float c = fmaxf(g_cnt3[k], 1.f);
    g_l3cat[k*256 + d] = g_sum3[k*256 + d] / c;
}

__global__ void k_root(){
    int d = threadIdx.x;
    float s = 0.f;
    for (int k = 0; k < 100; k++) s += g_l3cat[k*256 + d];
    g_rootcat[d] = s * 0.01f;
    g_rootcat[256 + d] = 0.f;
}

__global__ void k_bidx(const int* l3){
    int i = blockIdx.x*256 + threadIdx.x;
    if (i < 101)  g_i01[i] = (i < 100) ? 0 : 1;
    if (i < 1001) g_i3[i]  = (i < 1000) ? l3[i] : 100;
}

__global__ void k_tok(const int* src, const int* l2, const int* l3, const float* embed){
    int t = blockIdx.x, d = threadIdx.x;
    int tok = src[t];
    bool msk = (tok == 0);
    g_X0[(size_t)t*256 + d] = msk ? 0.f : embed[(size_t)tok*256 + d];
    if (d == 0){
        int j = msk ? 1000 : l2[tok];
        g_sidx[t] = j;
        g_iF3[t]  = msk ? 100 : l3[l2[tok]];
        g_iFr[t]  = msk ? 1 : 0;
    }
}

// ------------------------- generic GEMM (+ fused LSTM) -------------------------
// C[M,1024] = gather(A)[M,256] @ W[1024,256]^T   (W gate-permuted)
// Zout != 0 : plain mode, write Z to Zout[M,1024]
// else LSTM : z += Xadd[xIdx[r]] + bias; c = sig(f)*cp + sig(i)*tanh(g); h = sig(o)*tanh(c)
__global__ void __launch_bounds__(256,2) k_gemm(
    const float* __restrict__ A, const int* __restrict__ aIdx,
    const float* __restrict__ W,
    const float* __restrict__ Xadd, const int* __restrict__ xIdx,
    const float* __restrict__ bias,
    const float* __restrict__ Cprev, const int* __restrict__ cIdx,
    float* Hout, int hStride, int hOff, float* Cout, float* Zout, int M)
{
    __shared__ float As[128*36];
    __shared__ float Bs[128*36];
    int tid = threadIdx.x;
    int warp = tid >> 5, lane = tid & 31;
    int gid = lane >> 2, tg = lane & 3;
    int wr = warp >> 1, wc = warp & 1;           // 4x2 warp grid
    int m0 = blockIdx.x * 128, n0 = blockIdx.y * 128;

    float acc[2][8][4];
    #pragma unroll
    for (int mt=0; mt<2; mt++)
      #pragma unroll
      for (int nt=0; nt<8; nt++)
        #pragma unroll
        for (int q=0; q<4; q++) acc[mt][nt][q] = 0.f;

    for (int kt = 0; kt < 8; kt++){
        int kb = kt*32;
        #pragma unroll
        for (int i=0;i<4;i++){
            int lin = tid + i*256;
            int r = lin >> 3, c4 = (lin & 7) << 2;
            int grow = m0 + r;
            float4 v = make_float4(0.f,0.f,0.f,0.f);
            if (grow < M){
                int ar = aIdx ? aIdx[grow] : grow;
                v = *(const float4*)(A + (size_t)ar*256 + kb + c4);
            }
            float* s = &As[r*36 + c4];
            s[0]=tf32r(v.x); s[1]=tf32r(v.y); s[2]=tf32r(v.z); s[3]=tf32r(v.w);
        }
        #pragma unroll
        for (int i=0;i<4;i++){
            int lin = tid + i*256;
            int r = lin >> 3, c4 = (lin & 7) << 2;
            float4 v = *(const float4*)(W + (size_t)(n0 + r)*256 + kb + c4);
            float* s = &Bs[r*36 + c4];
            s[0]=tf32r(v.x); s[1]=tf32r(v.y); s[2]=tf32r(v.z); s[3]=tf32r(v.w);
        }
        __syncthreads();
        #pragma unroll
        for (int ks=0; ks<4; ks++){
            int k = ks*8;
            unsigned a[2][4], b[8][2];
            #pragma unroll
            for (int mt=0; mt<2; mt++){
                const float* p = &As[(wr*32 + mt*16 + gid)*36 + k + tg];
                a[mt][0]=__float_as_uint(p[0]);    a[mt][1]=__float_as_uint(p[8*36]);
                a[mt][2]=__float_as_uint(p[4]);    a[mt][3]=__float_as_uint(p[8*36+4]);
            }
            #pragma unroll
            for (int nt=0; nt<8; nt++){
                const float* q = &Bs[(wc*64 + nt*8 + gid)*36 + k + tg];
                b[nt][0]=__float_as_uint(q[0]);    b[nt][1]=__float_as_uint(q[4]);
            }
            #pragma unroll
            for (int mt=0; mt<2; mt++)
              #pragma unroll
              for (int nt=0; nt<8; nt++)
                mma8(acc[mt][nt], a[mt], b[nt]);
        }
        __syncthreads();
    }

    // epilogue via per-warp smem slab (32 rows x 32 cols, ld 36), two col passes
    float* slab = &As[0] + warp*1152;            // 8 warps x 1152 floats = 9216 (fits As+Bs)
    #pragma unroll
    for (int pass = 0; pass < 2; pass++){
        #pragma unroll
        for (int mt=0; mt<2; mt++)
          #pragma unroll
          for (int ntl=0; ntl<4; ntl++){
            int nt = pass*4 + ntl;
            int rr = mt*16 + gid, cc = ntl*8 + tg*2;
            slab[rr*36 + cc]       = acc[mt][nt][0];
            slab[rr*36 + cc + 1]   = acc[mt][nt][1];
            slab[(rr+8)*36 + cc]   = acc[mt][nt][2];
            slab[(rr+8)*36 + cc+1] = acc[mt][nt][3];
          }
        __syncwarp();
        int u = lane & 7, rq = lane >> 3;        // 8 local units, 4-row groups
        #pragma unroll
        for (int it=0; it<8; it++){
            int r = it*4 + rq;
            int grow = m0 + wr*32 + r;
            if (grow < M){
                float4 z = *(const float4*)&slab[r*36 + u*4];
                int gcol = n0 + wc*64 + pass*32 + u*4;
                if (Zout){
                    *(float4*)(Zout + (size_t)grow*1024 + gcol) = z;
                } else {
                    float4 bb = *(const float4*)(bias + gcol);
                    z.x += bb.x; z.y += bb.y; z.z += bb.z; z.w += bb.w;
                    if (Xadd){
                        int xr = xIdx ? xIdx[grow] : grow;
                        float4 xa = *(const float4*)(Xadd + (size_t)xr*1024 + gcol);
                        z.x += xa.x; z.y += xa.y; z.z += xa.z; z.w += xa.w;
                    }
                    int gunit = gcol >> 2;
                    float cp = 0.f;
                    if (Cprev){
                        int cr = cIdx ? cIdx[grow] : grow;
                        cp = Cprev[(size_t)cr*256 + gunit];
                    }
                    float c = sigf(z.y)*cp + sigf(z.x)*tanhfast(z.z);
                    float h = sigf(z.w)*tanhfast(c);
                    Hout[(size_t)grow*hStride + hOff + gunit] = h;
                    if (Cout) Cout[(size_t)grow*256 + gunit] = c;
                }
            }
        }
        __syncwarp();
    }
}

// ------------------------- host -------------------------
static void* sym(const void* s){ void* p = nullptr; cudaGetSymbolAddress(&p, s); return p; }

extern "C" void kernel_launch(void* const* d_in, const int* in_sizes, int n_in,
                              void* d_out, int out_size)
{
    const int*   src   = (const int*)  d_in[0];
    const int*   l2    = (const int*)  d_in[1];
    const int*   l3    = (const int*)  d_in[2];
    const float* embed = (const float*)d_in[3];
    const float* wihf  = (const float*)d_in[4];
    const float* whhf  = (const float*)d_in[5];
    const float* bihf  = (const float*)d_in[6];
    const float* bhhf  = (const float*)d_in[7];
    const float* wihb  = (const float*)d_in[8];
    const float* whhb  = (const float*)d_in[9];
    const float* bihb  = (const float*)d_in[10];
    const float* bhhb  = (const float*)d_in[11];
    float* out = (float*)d_out;

    float *Wihf=(float*)sym(g_Wihf), *Whhf=(float*)sym(g_Whhf);
    float *Wihb=(float*)sym(g_Wihb), *Whhb=(float*)sym(g_Whhb);
    float *bf=(float*)sym(g_bf), *bb=(float*)sym(g_bb);
    float *l2cat=(float*)sym(g_l2cat), *l3cat=(float*)sym(g_l3cat), *rootcat=(float*)sym(g_rootcat);
    float *P2f=(float*)sym(g_P2f), *P3f=(float*)sym(g_P3f), *Prf=(float*)sym(g_Prf);
    float *P2b=(float*)sym(g_P2b), *P3b=(float*)sym(g_P3b), *Prb=(float*)sym(g_Prb);
    float *h1=(float*)sym(g_h1), *c1=(float*)sym(g_c1), *h2=(float*)sym(g_h2), *c2=(float*)sym(g_c2);
    float *h3=(float*)sym(g_h3), *c3=(float*)sym(g_c3), *HPb=(float*)sym(g_HPb);
    int *i01=(int*)sym(g_i01), *i3=(int*)sym(g_i3);
    float *X0=(float*)sym(g_X0);
    int *sidx=(int*)sym(g_sidx), *iF3=(int*)sym(g_iF3), *iFr=(int*)sym(g_iFr);
    float *Ha=(float*)sym(g_Ha), *Ca=(float*)sym(g_Ca), *Hc=(float*)sym(g_Hc), *Cc=(float*)sym(g_Cc);

    // prep
    k_zero<<<1000,256>>>();
    k_prep<<<1024,256>>>(wihf, whhf, bihf, bhhf, Wihf, Whhf, bf);
    k_prep<<<1024,256>>>(wihb, whhb, bihb, bhhb, Wihb, Whhb, bb);
    k_seg2<<<VV,256>>>(embed, l2);
    k_lvl2<<<1001,256>>>(l3);
    k_lvl3<<<101,256>>>();
    k_root<<<1,256>>>();
    k_bidx<<<5,256>>>(l3);
    k_tok<<<NTOK,256>>>(src, l2, l3, embed);

    dim3 gBig((NTOK+127)/128, 8), gS1(1,8), gS101(1,8), gS1001(8,8);

    // x-projection tables (plain mode)
    k_gemm<<<gS1001,256>>>(l2cat, 0, Wihf, 0,0,0,0,0, 0,0,0,0, P2f, 1001);
    k_gemm<<<gS101 ,256>>>(l3cat, 0, Wihf, 0,0,0,0,0, 0,0,0,0, P3f, 101);
    k_gemm<<<gS1   ,256>>>(rootcat,0, Wihf, 0,0,0,0,0, 0,0,0,0, Prf, 2);
    k_gemm<<<gS1001,256>>>(l2cat, 0, Wihb, 0,0,0,0,0, 0,0,0,0, P2b, 1001);
    k_gemm<<<gS101 ,256>>>(l3cat, 0, Wihb, 0,0,0,0,0, 0,0,0,0, P3b, 101);
    k_gemm<<<gS1   ,256>>>(rootcat,0, Wihb, 0,0,0,0,0, 0,0,0,0, Prb, 2);

    // backward chain over distinct states (root -> level3 -> level2)
    k_gemm<<<gS1   ,256>>>(rootcat,0, Wihb, 0,0,   bb, 0,0,   h1,256,0, c1, 0, 2);
    k_gemm<<<gS101 ,256>>>(h1, i01,  Whhb, P3b,0,  bb, c1,i01, h2,256,0, c2, 0, 101);
    k_gemm<<<gS1001,256>>>(h2, i3,   Whhb, P2b,0,  bb, c2,i3,  h3,256,0, c3, 0, 1001);
    k_gemm<<<gS1001,256>>>(h3, 0,    Whhb, 0,0,0,0,0, 0,0,0,0, HPb, 1001);

    // forward LSTM (big)
    k_gemm<<<gBig,256>>>(X0, 0, Wihf, 0,0,      bf, 0,0,    Ha,256,0, Ca, 0, NTOK);
    k_gemm<<<gBig,256>>>(Ha, 0, Whhf, P2f,sidx, bf, Ca,0,   Hc,256,0, Cc, 0, NTOK);
    k_gemm<<<gBig,256>>>(Hc, 0, Whhf, P3f,iF3,  bf, Cc,0,   Ha,256,0, Ca, 0, NTOK);
    k_gemm<<<gBig,256>>>(Ha, 0, Whhf, Prf,iFr,  bf, Ca,0,   out,512,0, 0,  0, NTOK);

    // backward final step (big)
    k_gemm<<<gBig,256>>>(X0, 0, Wihb, HPb,sidx, bb, c3,sidx, out,512,256, 0, 0, NTOK);
}